// round 6
// baseline (speedup 1.0000x reference)
#include <cuda_runtime.h>
#include <math.h>

#define N_NODES  100000
#define N_EDGES  1600000
#define N_GRAPHS 2000
#define D_IN     768
#define D_H      128
#define D_MLP    32
#define D_OUT    2

// ---------------- device scratch (allocation-free) ----------------
__device__ int   g_is64;            // 1 if edge_index/batch are int64 on device
__device__ float g_deg [N_NODES];
__device__ float g_dinv[N_NODES];
__device__ float g_norm[N_EDGES];
__device__ int   g_row [N_EDGES];
__device__ int   g_col [N_EDGES];

__device__ float g_Wcat1[D_IN * 2 * D_H];   // [768][256] = [W1i | W1r]
__device__ float g_Wcat2[D_H  * 2 * D_H];   // [128][256] = [W2i | W2r]

// Aliased across the two ARMA layers (layer 2 reuses layer 1's, keeping the
// edge-pass working set L2-resident across both passes).
__device__ float g_hbuf[(size_t)N_NODES * D_H];  // x@Wi result
__device__ float g_xr  [(size_t)N_NODES * D_H];  // x@Wr result
__device__ float g_agg [(size_t)N_NODES * D_H];  // scatter target
__device__ float g_h   [(size_t)N_NODES * D_H];  // relu output of layer 1

__device__ float g_gsum[N_GRAPHS * D_H];
__device__ float g_gcnt[N_GRAPHS];

__device__ __forceinline__ int clampi(int v, int lo, int hi) {
    return min(max(v, lo), hi);
}

// ---------------- kernels ----------------

// Detect int64 vs int32 layout of edge_index. If int64 (values < 2^31),
// every odd 32-bit word is a zero high-word. If int32, odd words are node
// ids (~uniform in [0, 1e5)); 64 independent samples all being zero has
// probability ~1e-320. All sampled indices < 2E, in-bounds for both layouts.
__global__ void detect_kernel(const int* __restrict__ ei32) {
    if (threadIdx.x != 0 || blockIdx.x != 0) return;
    int nz = 0;
    #pragma unroll
    for (int j = 0; j < 64; j++) {
        long long idx = 2LL * j * 25000 + 1;   // odd, < 3.2M
        nz += (ei32[idx] != 0);
    }
    g_is64 = (nz == 0) ? 1 : 0;
}

__global__ void zero_all_kernel() {
    const long long stride = (long long)gridDim.x * blockDim.x;
    long long i = (long long)blockIdx.x * blockDim.x + threadIdx.x;
    const long long T = (long long)N_NODES * D_H;
    for (long long k = i; k < T; k += stride) g_agg[k] = 0.f;
    for (long long k = i; k < N_NODES; k += stride) g_deg[k] = 0.f;
    for (long long k = i; k < N_GRAPHS * D_H; k += stride) g_gsum[k] = 0.f;
    for (long long k = i; k < N_GRAPHS; k += stride) g_gcnt[k] = 0.f;
}

// decode edge indices (either layout) -> int32 (clamped), accumulate
// weighted in-degree on col
__global__ void prep_edges_kernel(const int* __restrict__ ei32,
                                  const float* __restrict__ ea) {
    int e = blockIdx.x * blockDim.x + threadIdx.x;
    if (e >= N_EDGES) return;
    int r, c;
    if (g_is64) {   // int64 little-endian: low word at 2*k
        r = ei32[2LL * e];
        c = ei32[2LL * (N_EDGES + e)];
    } else {
        r = ei32[e];
        c = ei32[(size_t)N_EDGES + e];
    }
    r = clampi(r, 0, N_NODES - 1);
    c = clampi(c, 0, N_NODES - 1);
    g_row[e] = r;
    g_col[e] = c;
    atomicAdd(&g_deg[c], ea[e]);
}

__global__ void dinv_kernel() {
    int i = blockIdx.x * blockDim.x + threadIdx.x;
    if (i >= N_NODES) return;
    float d = g_deg[i];
    g_dinv[i] = (d > 0.f) ? rsqrtf(d) : 0.f;
}

__global__ void norm_kernel(const float* __restrict__ ea) {
    int e = blockIdx.x * blockDim.x + threadIdx.x;
    if (e >= N_EDGES) return;
    g_norm[e] = g_dinv[g_row[e]] * ea[e] * g_dinv[g_col[e]];
}

// pack [W_i | W_r] into one [K][256] matrix for each layer
__global__ void pack_w_kernel(const float* __restrict__ W1i, const float* __restrict__ W1r,
                              const float* __restrict__ W2i, const float* __restrict__ W2r) {
    int i = blockIdx.x * blockDim.x + threadIdx.x;
    const int T1 = D_IN * 2 * D_H;
    const int T2 = D_H * 2 * D_H;
    if (i < T1) {
        int row = i / (2 * D_H), c = i % (2 * D_H);
        g_Wcat1[i] = (c < D_H) ? W1i[row * D_H + c] : W1r[row * D_H + (c - D_H)];
    } else if (i < T1 + T2) {
        int j = i - T1;
        int row = j / (2 * D_H), c = j % (2 * D_H);
        g_Wcat2[j] = (c < D_H) ? W2i[row * D_H + c] : W2r[row * D_H + (c - D_H)];
    }
}

// Classic 128x128x8 fp32 SGEMM, 256 threads, 8x8 per thread.
// which==0: A = x (param), B = Wcat1, K = 768
// which==1: A = g_h,       B = Wcat2, K = 128
// blockIdx.x (0/1) selects the [Wi | Wr] output half -> g_hbuf / g_xr.
__global__ void __launch_bounds__(256, 2)
sgemm_kernel(const float* __restrict__ Ain, int which, int M, int K) {
    const float* A = (which == 0) ? Ain : g_h;
    const float* B = (which == 0) ? g_Wcat1 : g_Wcat2;
    float* C = (blockIdx.x == 0) ? g_hbuf : g_xr;

    __shared__ float As[8][128];
    __shared__ float Bs[8][128];

    const int tid  = threadIdx.x;
    const int arow = tid >> 1;            // 0..127
    const int acol = (tid & 1) << 2;      // 0 or 4
    const int brl  = tid >> 5;            // 0..7
    const int bcl  = (tid & 31) << 2;     // 0..124
    const int row0 = blockIdx.y * 128;
    const bool aval = (row0 + arow) < M;

    const float* Ap = A + (size_t)(row0 + arow) * K + acol;
    const float* Bp = B + (size_t)brl * 256 + blockIdx.x * 128 + bcl;

    const int tr = (tid >> 4) << 3;       // 0..120
    const int tc = (tid & 15) << 3;       // 0..120

    float acc[8][8];
    #pragma unroll
    for (int i = 0; i < 8; i++)
        #pragma unroll
        for (int j = 0; j < 8; j++) acc[i][j] = 0.f;

    for (int k0 = 0; k0 < K; k0 += 8) {
        float4 av = aval ? *(const float4*)Ap : make_float4(0.f, 0.f, 0.f, 0.f);
        As[acol + 0][arow] = av.x;
        As[acol + 1][arow] = av.y;
        As[acol + 2][arow] = av.z;
        As[acol + 3][arow] = av.w;
        *(float4*)&Bs[brl][bcl] = *(const float4*)Bp;
        __syncthreads();

        #pragma unroll
        for (int kk = 0; kk < 8; kk++) {
            float ar[8], br[8];
            #pragma unroll
            for (int i = 0; i < 8; i++) ar[i] = As[kk][tr + i];
            #pragma unroll
            for (int j = 0; j < 8; j++) br[j] = Bs[kk][tc + j];
            #pragma unroll
            for (int i = 0; i < 8; i++)
                #pragma unroll
                for (int j = 0; j < 8; j++)
                    acc[i][j] += ar[i] * br[j];
        }
        __syncthreads();
        Ap += 8;
        Bp += 8 * 256;
    }

    #pragma unroll
    for (int i = 0; i < 8; i++) {
        int r = row0 + tr + i;
        if (r < M) {
            float4* cp = (float4*)(C + (size_t)r * D_H + tc);
            cp[0] = make_float4(acc[i][0], acc[i][1], acc[i][2], acc[i][3]);
            cp[1] = make_float4(acc[i][4], acc[i][5], acc[i][6], acc[i][7]);
        }
    }
}

// one thread per (edge, 4-column chunk): 32 threads (one warp) per edge.
// Vector load from source row, 4 scalar atomics to destination row.
__global__ void edge_msg_kernel() {
    long long i = (long long)blockIdx.x * blockDim.x + threadIdx.x;
    if (i >= (long long)N_EDGES * 32) return;
    int e  = (int)(i >> 5);
    int c4 = (int)(i & 31);
    int r = g_row[e];
    int c = g_col[e];
    float nm = g_norm[e];
    float4 v = ((const float4*)(g_hbuf + (size_t)r * D_H))[c4];
    float* dst = g_agg + (size_t)c * D_H + c4 * 4;
    atomicAdd(dst + 0, v.x * nm);
    atomicAdd(dst + 1, v.y * nm);
    atomicAdd(dst + 2, v.z * nm);
    atomicAdd(dst + 3, v.w * nm);
}

// h = relu(agg + xr + b1)   (the reference's elu(relu(.)) == relu(.))
// Also re-zeroes g_agg in place for the second edge pass.
__global__ void act1_kernel(const float* __restrict__ b1) {
    long long i = (long long)blockIdx.x * blockDim.x + threadIdx.x;
    if (i >= (long long)N_NODES * 32) return;
    int j4 = (int)(i & 31);
    float4 a = ((const float4*)g_agg)[i];
    float4 x = ((const float4*)g_xr)[i];
    float4 b = ((const float4*)b1)[j4];
    float4 v;
    v.x = fmaxf(a.x + x.x + b.x, 0.f);
    v.y = fmaxf(a.y + x.y + b.y, 0.f);
    v.z = fmaxf(a.z + x.z + b.z, 0.f);
    v.w = fmaxf(a.w + x.w + b.w, 0.f);
    ((float4*)g_h)[i] = v;
    ((float4*)g_agg)[i] = make_float4(0.f, 0.f, 0.f, 0.f);
}

// node_x = relu(agg + xr + b2); pool into per-graph sums + counts
__global__ void act2_pool_kernel(const float* __restrict__ b2,
                                 const int* __restrict__ bat32) {
    long long i = (long long)blockIdx.x * blockDim.x + threadIdx.x;
    if (i >= (long long)N_NODES * 32) return;
    int n  = (int)(i >> 5);
    int j4 = (int)(i & 31);
    float4 a = ((const float4*)g_agg)[i];
    float4 x = ((const float4*)g_xr)[i];
    float4 b = ((const float4*)b2)[j4];
    float4 v;
    v.x = fmaxf(a.x + x.x + b.x, 0.f);
    v.y = fmaxf(a.y + x.y + b.y, 0.f);
    v.z = fmaxf(a.z + x.z + b.z, 0.f);
    v.w = fmaxf(a.w + x.w + b.w, 0.f);
    int g = g_is64 ? bat32[2LL * n] : bat32[n];   // low word if int64
    g = clampi(g, 0, N_GRAPHS - 1);
    float* dst = g_gsum + (size_t)g * D_H + j4 * 4;
    atomicAdd(dst + 0, v.x);
    atomicAdd(dst + 1, v.y);
    atomicAdd(dst + 2, v.z);
    atomicAdd(dst + 3, v.w);
    if (j4 == 0) atomicAdd(&g_gcnt[g], 1.0f);
}

// per-graph head: mean -> elu(mean@Wl1+bl1) -> @Wl2+bl2
__global__ void head_kernel(const float* __restrict__ Wl1, const float* __restrict__ bl1,
                            const float* __restrict__ Wl2, const float* __restrict__ bl2,
                            float* __restrict__ out) {
    int g = blockIdx.x;
    int k = threadIdx.x;   // 32 threads, one per D_MLP unit
    __shared__ float mean[D_H];
    float inv = 1.0f / fmaxf(g_gcnt[g], 1.0f);
    for (int j = k; j < D_H; j += 32) mean[j] = g_gsum[g * D_H + j] * inv;
    __syncwarp();
    float t = bl1[k];
    #pragma unroll 8
    for (int j = 0; j < D_H; j++) t += mean[j] * Wl1[j * D_MLP + k];
    t = (t > 0.f) ? t : expm1f(t);   // ELU (input can be negative here)
    float o0 = t * Wl2[k * D_OUT + 0];
    float o1 = t * Wl2[k * D_OUT + 1];
    #pragma unroll
    for (int off = 16; off; off >>= 1) {
        o0 += __shfl_down_sync(0xffffffffu, o0, off);
        o1 += __shfl_down_sync(0xffffffffu, o1, off);
    }
    if (k == 0) {
        out[g * D_OUT + 0] = o0 + bl2[0];
        out[g * D_OUT + 1] = o1 + bl2[1];
    }
}

// ---------------- launch ----------------
extern "C" void kernel_launch(void* const* d_in, const int* in_sizes, int n_in,
                              void* d_out, int out_size) {
    const float* x     = (const float*)d_in[0];
    const int*   ei32  = (const int*)d_in[1];     // int32 or int64 (auto-detected)
    const float* ea    = (const float*)d_in[2];
    const int*   bat32 = (const int*)d_in[3];     // same layout as edge_index
    // num_graphs may or may not be materialized as a 1-element input.
    int base = (n_in >= 15 && in_sizes[4] <= 2) ? 5 : 4;
    const float* W1i = (const float*)d_in[base + 0];
    const float* W1r = (const float*)d_in[base + 1];
    const float* b1  = (const float*)d_in[base + 2];
    const float* W2i = (const float*)d_in[base + 3];
    const float* W2r = (const float*)d_in[base + 4];
    const float* b2  = (const float*)d_in[base + 5];
    const float* Wl1 = (const float*)d_in[base + 6];
    const float* bl1 = (const float*)d_in[base + 7];
    const float* Wl2 = (const float*)d_in[base + 8];
    const float* bl2 = (const float*)d_in[base + 9];
    float* out = (float*)d_out;

    const int TPB = 256;

    detect_kernel<<<1, 32>>>(ei32);
    zero_all_kernel<<<2048, TPB>>>();
    prep_edges_kernel<<<(N_EDGES + TPB - 1) / TPB, TPB>>>(ei32, ea);
    dinv_kernel<<<(N_NODES + TPB - 1) / TPB, TPB>>>();
    norm_kernel<<<(N_EDGES + TPB - 1) / TPB, TPB>>>(ea);
    {
        int tot = D_IN * 2 * D_H + D_H * 2 * D_H;
        pack_w_kernel<<<(tot + TPB - 1) / TPB, TPB>>>(W1i, W1r, W2i, W2r);
    }

    dim3 gg(2, (N_NODES + 127) / 128);
    long long ethreads = (long long)N_EDGES * 32;
    long long nthreads = (long long)N_NODES * 32;
    unsigned eg = (unsigned)((ethreads + TPB - 1) / TPB);
    unsigned ng = (unsigned)((nthreads + TPB - 1) / TPB);

    // layer 1
    sgemm_kernel<<<gg, 256>>>(x, 0, N_NODES, D_IN);
    edge_msg_kernel<<<eg, TPB>>>();
    act1_kernel<<<ng, TPB>>>(b1);          // also re-zeroes g_agg

    // layer 2 (reuses g_hbuf / g_xr / g_agg)
    sgemm_kernel<<<gg, 256>>>(x, 1, N_NODES, D_H);
    edge_msg_kernel<<<eg, TPB>>>();
    act2_pool_kernel<<<ng, TPB>>>(b2, bat32);

    head_kernel<<<N_GRAPHS, 32>>>(Wl1, bl1, Wl2, bl2, out);
}

// round 8
// speedup vs baseline: 1.5330x; 1.5330x over previous
#include <cuda_runtime.h>
#include <math.h>

#define N_NODES  100000
#define N_EDGES  1600000
#define N_GRAPHS 2000
#define D_IN     768
#define D_H      128
#define D_MLP    32
#define D_OUT    2

#define SCAN_BS  512
#define SCAN_NB  ((N_NODES + SCAN_BS - 1) / SCAN_BS)

// ---------------- device scratch (allocation-free) ----------------
__device__ int   g_is64;            // 1 if edge_index/batch are int64 on device
__device__ float g_deg [N_NODES];   // weighted in-degree
__device__ float g_dinv[N_NODES];
__device__ int   g_row [N_EDGES];
__device__ int   g_col [N_EDGES];

// CSR (edges sorted by destination node)
__device__ int   g_cnt [N_NODES];       // int in-degree histogram
__device__ int   g_off [N_NODES + 1];   // exclusive prefix
__device__ int   g_cur [N_NODES];       // scatter cursors
__device__ int   g_bsum[SCAN_NB];
__device__ int   g_srow [N_EDGES];      // source row, sorted by dst
__device__ float g_snorm[N_EDGES];      // edge norm, sorted by dst

__device__ float g_Wcat1[D_IN * 2 * D_H];   // [768][256] = [W1i | W1r]
__device__ float g_Wcat2[D_H  * 2 * D_H];   // [128][256] = [W2i | W2r]

// Aliased across the two ARMA layers.
__device__ float g_hbuf[(size_t)N_NODES * D_H];  // x@Wi result
__device__ float g_xr  [(size_t)N_NODES * D_H];  // x@Wr result
__device__ float g_h   [(size_t)N_NODES * D_H];  // relu output of layer 1

__device__ float g_gsum[N_GRAPHS * D_H];
__device__ float g_gcnt[N_GRAPHS];

__device__ __forceinline__ int clampi(int v, int lo, int hi) {
    return min(max(v, lo), hi);
}

// ---------------- kernels ----------------

// Detect int64 vs int32 layout of edge_index (all odd 32-bit words zero => int64).
__global__ void detect_kernel(const int* __restrict__ ei32) {
    if (threadIdx.x != 0 || blockIdx.x != 0) return;
    int nz = 0;
    #pragma unroll
    for (int j = 0; j < 64; j++) {
        long long idx = 2LL * j * 25000 + 1;   // odd, < 3.2M
        nz += (ei32[idx] != 0);
    }
    g_is64 = (nz == 0) ? 1 : 0;
}

__global__ void zero_all_kernel() {
    const long long stride = (long long)gridDim.x * blockDim.x;
    long long i = (long long)blockIdx.x * blockDim.x + threadIdx.x;
    for (long long k = i; k < N_NODES; k += stride) { g_deg[k] = 0.f; g_cnt[k] = 0; }
    for (long long k = i; k < N_GRAPHS * D_H; k += stride) g_gsum[k] = 0.f;
    for (long long k = i; k < N_GRAPHS; k += stride) g_gcnt[k] = 0.f;
}

// decode edge indices (either layout), weighted degree + count histogram
__global__ void prep_edges_kernel(const int* __restrict__ ei32,
                                  const float* __restrict__ ea) {
    int e = blockIdx.x * blockDim.x + threadIdx.x;
    if (e >= N_EDGES) return;
    int r, c;
    if (g_is64) {   // int64 little-endian: low word at 2*k
        r = ei32[2LL * e];
        c = ei32[2LL * (N_EDGES + e)];
    } else {
        r = ei32[e];
        c = ei32[(size_t)N_EDGES + e];
    }
    r = clampi(r, 0, N_NODES - 1);
    c = clampi(c, 0, N_NODES - 1);
    g_row[e] = r;
    g_col[e] = c;
    atomicAdd(&g_deg[c], ea[e]);
    atomicAdd(&g_cnt[c], 1);
}

__global__ void dinv_kernel() {
    int i = blockIdx.x * blockDim.x + threadIdx.x;
    if (i >= N_NODES) return;
    float d = g_deg[i];
    g_dinv[i] = (d > 0.f) ? rsqrtf(d) : 0.f;
}

// ---- 3-phase block scan of g_cnt -> g_off ----
__global__ void scan1_kernel() {
    __shared__ int s[SCAN_BS];
    int tid = threadIdx.x;
    int i = blockIdx.x * SCAN_BS + tid;
    int v = (i < N_NODES) ? g_cnt[i] : 0;
    s[tid] = v;
    __syncthreads();
    for (int d = 1; d < SCAN_BS; d <<= 1) {
        int t = (tid >= d) ? s[tid - d] : 0;
        __syncthreads();
        s[tid] += t;
        __syncthreads();
    }
    if (i < N_NODES) g_off[i] = s[tid] - v;      // exclusive within block
    if (tid == SCAN_BS - 1) g_bsum[blockIdx.x] = s[tid];
}

__global__ void scan2_kernel() {
    if (threadIdx.x != 0 || blockIdx.x != 0) return;
    int acc = 0;
    for (int b = 0; b < SCAN_NB; b++) { int t = g_bsum[b]; g_bsum[b] = acc; acc += t; }
    g_off[N_NODES] = acc;    // == N_EDGES
}

__global__ void scan3_kernel() {
    int i = blockIdx.x * blockDim.x + threadIdx.x;
    if (i >= N_NODES) return;
    int o = g_off[i] + g_bsum[i / SCAN_BS];
    g_off[i] = o;
    g_cur[i] = o;
}

// place (row, norm) into CSR slots; norm computed inline
__global__ void scatter_kernel(const float* __restrict__ ea) {
    int e = blockIdx.x * blockDim.x + threadIdx.x;
    if (e >= N_EDGES) return;
    int r = g_row[e], c = g_col[e];
    float nm = g_dinv[r] * ea[e] * g_dinv[c];
    int pos = atomicAdd(&g_cur[c], 1);
    g_srow[pos]  = r;
    g_snorm[pos] = nm;
}

// pack [W_i | W_r] into one [K][256] matrix for each layer
__global__ void pack_w_kernel(const float* __restrict__ W1i, const float* __restrict__ W1r,
                              const float* __restrict__ W2i, const float* __restrict__ W2r) {
    int i = blockIdx.x * blockDim.x + threadIdx.x;
    const int T1 = D_IN * 2 * D_H;
    const int T2 = D_H * 2 * D_H;
    if (i < T1) {
        int row = i / (2 * D_H), c = i % (2 * D_H);
        g_Wcat1[i] = (c < D_H) ? W1i[row * D_H + c] : W1r[row * D_H + (c - D_H)];
    } else if (i < T1 + T2) {
        int j = i - T1;
        int row = j / (2 * D_H), c = j % (2 * D_H);
        g_Wcat2[j] = (c < D_H) ? W2i[row * D_H + c] : W2r[row * D_H + (c - D_H)];
    }
}

// Classic 128x128x8 fp32 SGEMM, 256 threads, 8x8 per thread.
// which==0: A = x (param), B = Wcat1, K = 768
// which==1: A = g_h,       B = Wcat2, K = 128
// blockIdx.x (0/1) selects the [Wi | Wr] output half -> g_hbuf / g_xr.
__global__ void __launch_bounds__(256, 2)
sgemm_kernel(const float* __restrict__ Ain, int which, int M, int K) {
    const float* A = (which == 0) ? Ain : g_h;
    const float* B = (which == 0) ? g_Wcat1 : g_Wcat2;
    float* C = (blockIdx.x == 0) ? g_hbuf : g_xr;

    __shared__ float As[8][128];
    __shared__ float Bs[8][128];

    const int tid  = threadIdx.x;
    const int arow = tid >> 1;
    const int acol = (tid & 1) << 2;
    const int brl  = tid >> 5;
    const int bcl  = (tid & 31) << 2;
    const int row0 = blockIdx.y * 128;
    const bool aval = (row0 + arow) < M;

    const float* Ap = A + (size_t)(row0 + arow) * K + acol;
    const float* Bp = B + (size_t)brl * 256 + blockIdx.x * 128 + bcl;

    const int tr = (tid >> 4) << 3;
    const int tc = (tid & 15) << 3;

    float acc[8][8];
    #pragma unroll
    for (int i = 0; i < 8; i++)
        #pragma unroll
        for (int j = 0; j < 8; j++) acc[i][j] = 0.f;

    for (int k0 = 0; k0 < K; k0 += 8) {
        float4 av = aval ? *(const float4*)Ap : make_float4(0.f, 0.f, 0.f, 0.f);
        As[acol + 0][arow] = av.x;
        As[acol + 1][arow] = av.y;
        As[acol + 2][arow] = av.z;
        As[acol + 3][arow] = av.w;
        *(float4*)&Bs[brl][bcl] = *(const float4*)Bp;
        __syncthreads();

        #pragma unroll
        for (int kk = 0; kk < 8; kk++) {
            float ar[8], br[8];
            #pragma unroll
            for (int i = 0; i < 8; i++) ar[i] = As[kk][tr + i];
            #pragma unroll
            for (int j = 0; j < 8; j++) br[j] = Bs[kk][tc + j];
            #pragma unroll
            for (int i = 0; i < 8; i++)
                #pragma unroll
                for (int j = 0; j < 8; j++)
                    acc[i][j] += ar[i] * br[j];
        }
        __syncthreads();
        Ap += 8;
        Bp += 8 * 256;
    }

    #pragma unroll
    for (int i = 0; i < 8; i++) {
        int r = row0 + tr + i;
        if (r < M) {
            float4* cp = (float4*)(C + (size_t)r * D_H + tc);
            cp[0] = make_float4(acc[i][0], acc[i][1], acc[i][2], acc[i][3]);
            cp[1] = make_float4(acc[i][4], acc[i][5], acc[i][6], acc[i][7]);
        }
    }
}

// Warp-per-node CSR gather, 2 edges in flight (MLP=2 on the L2-bound chain).
__device__ __forceinline__ float4 csr_gather(int node, int lane) {
    int e   = g_off[node];
    int end = g_off[node + 1];
    float4 acc = make_float4(0.f, 0.f, 0.f, 0.f);
    for (; e + 2 <= end; e += 2) {
        int   r0 = g_srow[e],     r1 = g_srow[e + 1];
        float n0 = g_snorm[e],    n1 = g_snorm[e + 1];
        float4 v0 = ((const float4*)(g_hbuf + (size_t)r0 * D_H))[lane];
        float4 v1 = ((const float4*)(g_hbuf + (size_t)r1 * D_H))[lane];
        acc.x += v0.x * n0 + v1.x * n1;
        acc.y += v0.y * n0 + v1.y * n1;
        acc.z += v0.z * n0 + v1.z * n1;
        acc.w += v0.w * n0 + v1.w * n1;
    }
    if (e < end) {
        int   r  = g_srow[e];
        float nm = g_snorm[e];
        float4 v = ((const float4*)(g_hbuf + (size_t)r * D_H))[lane];
        acc.x += v.x * nm; acc.y += v.y * nm;
        acc.z += v.z * nm; acc.w += v.w * nm;
    }
    return acc;
}

// layer 1: h = relu(gather + xr + b1)   (elu(relu(.)) == relu(.))
__global__ void gather_act1_kernel(const float* __restrict__ b1) {
    int warp = (blockIdx.x * blockDim.x + threadIdx.x) >> 5;
    if (warp >= N_NODES) return;
    int lane = threadIdx.x & 31;
    float4 acc = csr_gather(warp, lane);
    float4 x = ((const float4*)(g_xr + (size_t)warp * D_H))[lane];
    float4 b = ((const float4*)b1)[lane];
    float4 o;
    o.x = fmaxf(acc.x + x.x + b.x, 0.f);
    o.y = fmaxf(acc.y + x.y + b.y, 0.f);
    o.z = fmaxf(acc.z + x.z + b.z, 0.f);
    o.w = fmaxf(acc.w + x.w + b.w, 0.f);
    ((float4*)(g_h + (size_t)warp * D_H))[lane] = o;
}

// layer 2: relu + mean-pool scatter
__global__ void gather_act2_pool_kernel(const float* __restrict__ b2,
                                        const int* __restrict__ bat32) {
    int warp = (blockIdx.x * blockDim.x + threadIdx.x) >> 5;
    if (warp >= N_NODES) return;
    int lane = threadIdx.x & 31;
    float4 acc = csr_gather(warp, lane);
    float4 x = ((const float4*)(g_xr + (size_t)warp * D_H))[lane];
    float4 b = ((const float4*)b2)[lane];
    float4 o;
    o.x = fmaxf(acc.x + x.x + b.x, 0.f);
    o.y = fmaxf(acc.y + x.y + b.y, 0.f);
    o.z = fmaxf(acc.z + x.z + b.z, 0.f);
    o.w = fmaxf(acc.w + x.w + b.w, 0.f);
    int g = g_is64 ? bat32[2LL * warp] : bat32[warp];
    g = clampi(g, 0, N_GRAPHS - 1);
    float* dst = g_gsum + (size_t)g * D_H + lane * 4;
    atomicAdd(dst + 0, o.x);
    atomicAdd(dst + 1, o.y);
    atomicAdd(dst + 2, o.z);
    atomicAdd(dst + 3, o.w);
    if (lane == 0) atomicAdd(&g_gcnt[g], 1.0f);
}

// per-graph head: mean -> elu(mean@Wl1+bl1) -> @Wl2+bl2
__global__ void head_kernel(const float* __restrict__ Wl1, const float* __restrict__ bl1,
                            const float* __restrict__ Wl2, const float* __restrict__ bl2,
                            float* __restrict__ out) {
    int g = blockIdx.x;
    int k = threadIdx.x;   // 32 threads, one per D_MLP unit
    __shared__ float mean[D_H];
    float inv = 1.0f / fmaxf(g_gcnt[g], 1.0f);
    for (int j = k; j < D_H; j += 32) mean[j] = g_gsum[g * D_H + j] * inv;
    __syncwarp();
    float t = bl1[k];
    #pragma unroll 8
    for (int j = 0; j < D_H; j++) t += mean[j] * Wl1[j * D_MLP + k];
    t = (t > 0.f) ? t : expm1f(t);   // ELU
    float o0 = t * Wl2[k * D_OUT + 0];
    float o1 = t * Wl2[k * D_OUT + 1];
    #pragma unroll
    for (int off = 16; off; off >>= 1) {
        o0 += __shfl_down_sync(0xffffffffu, o0, off);
        o1 += __shfl_down_sync(0xffffffffu, o1, off);
    }
    if (k == 0) {
        out[g * D_OUT + 0] = o0 + bl2[0];
        out[g * D_OUT + 1] = o1 + bl2[1];
    }
}

// ---------------- launch ----------------
extern "C" void kernel_launch(void* const* d_in, const int* in_sizes, int n_in,
                              void* d_out, int out_size) {
    const float* x     = (const float*)d_in[0];
    const int*   ei32  = (const int*)d_in[1];     // int32 or int64 (auto-detected)
    const float* ea    = (const float*)d_in[2];
    const int*   bat32 = (const int*)d_in[3];     // same layout as edge_index
    int base = (n_in >= 15 && in_sizes[4] <= 2) ? 5 : 4;
    const float* W1i = (const float*)d_in[base + 0];
    const float* W1r = (const float*)d_in[base + 1];
    const float* b1  = (const float*)d_in[base + 2];
    const float* W2i = (const float*)d_in[base + 3];
    const float* W2r = (const float*)d_in[base + 4];
    const float* b2  = (const float*)d_in[base + 5];
    const float* Wl1 = (const float*)d_in[base + 6];
    const float* bl1 = (const float*)d_in[base + 7];
    const float* Wl2 = (const float*)d_in[base + 8];
    const float* bl2 = (const float*)d_in[base + 9];
    float* out = (float*)d_out;

    const int TPB = 256;
    const unsigned egrid = (N_EDGES + TPB - 1) / TPB;
    const unsigned ngrid = (N_NODES + TPB - 1) / TPB;

    detect_kernel<<<1, 32>>>(ei32);
    zero_all_kernel<<<1024, TPB>>>();
    prep_edges_kernel<<<egrid, TPB>>>(ei32, ea);
    dinv_kernel<<<ngrid, TPB>>>();

    // CSR build
    scan1_kernel<<<SCAN_NB, SCAN_BS>>>();
    scan2_kernel<<<1, 32>>>();
    scan3_kernel<<<ngrid, TPB>>>();
    scatter_kernel<<<egrid, TPB>>>(ea);

    {
        int tot = D_IN * 2 * D_H + D_H * 2 * D_H;
        pack_w_kernel<<<(tot + TPB - 1) / TPB, TPB>>>(W1i, W1r, W2i, W2r);
    }

    dim3 gg(2, (N_NODES + 127) / 128);
    unsigned wgrid = (unsigned)(((long long)N_NODES * 32 + TPB - 1) / TPB);

    // layer 1
    sgemm_kernel<<<gg, 256>>>(x, 0, N_NODES, D_IN);
    gather_act1_kernel<<<wgrid, TPB>>>(b1);

    // layer 2
    sgemm_kernel<<<gg, 256>>>(x, 1, N_NODES, D_H);
    gather_act2_pool_kernel<<<wgrid, TPB>>>(b2, bat32);

    head_kernel<<<N_GRAPHS, 32>>>(Wl1, bl1, Wl2, bl2, out);
}